// round 15
// baseline (speedup 1.0000x reference)
#include <cuda_runtime.h>
#include <cuda_fp16.h>

#define L_SEQ  2048
#define BATCH  2
#define DMODEL 1024
#define NHEADS 16
#define DK     64
#define E3     3072
#define NROWS  4096

// fp32 QKV projection scratch: [NROWS][E3], row r = l*BATCH + b, col e = h*192 + {q,k,v}
__device__ float g_qkv[NROWS * E3];

// fp16 operands for the projection GEMM
__device__ __align__(16) __half g_xh[NROWS * DMODEL];
__device__ __align__(16) __half g_wh[E3 * DMODEL];

// Attention operands: Q hi/lo fp16 (rope + 0.125*log2e), K fp16 (rope), V fp16 [b][h][d][l].
#define QKV_ELEMS (BATCH * NHEADS * L_SEQ * DK)
__device__ __align__(16) __half g_qhi[QKV_ELEMS];
__device__ __align__(16) __half g_qlo[QKV_ELEMS];
__device__ __align__(16) __half g_kh [QKV_ELEMS];
__device__ __align__(16) __half g_vh [QKV_ELEMS];

__constant__ float c_theta[16] = {
    1.0f,                     0.5623413251903491f,     0.31622776601683794f,   0.17782794100389228f,
    0.1f,                     0.05623413251903491f,    0.031622776601683794f,  0.017782794100389228f,
    0.01f,                    0.005623413251903491f,   0.0031622776601683794f, 0.0017782794100389228f,
    0.001f,                   0.0005623413251903491f,  0.00031622776601683794f,0.00017782794100389227f
};

// ---------------------------------------------------------------------------
// Helpers
// ---------------------------------------------------------------------------
#define MMA_F16(C, A, B)                                                         \
    asm volatile("mma.sync.aligned.m16n8k16.row.col.f32.f16.f16.f32 "            \
                 "{%0,%1,%2,%3}, {%4,%5,%6,%7}, {%8,%9}, {%0,%1,%2,%3};"         \
                 : "+f"((C)[0]), "+f"((C)[1]), "+f"((C)[2]), "+f"((C)[3])        \
                 : "r"((A)[0]), "r"((A)[1]), "r"((A)[2]), "r"((A)[3]),           \
                   "r"((B)[0]), "r"((B)[1]))

__device__ __forceinline__ void ldm4(unsigned* r, unsigned a) {
    asm volatile("ldmatrix.sync.aligned.m8n8.x4.shared.b16 {%0,%1,%2,%3}, [%4];"
                 : "=r"(r[0]), "=r"(r[1]), "=r"(r[2]), "=r"(r[3]) : "r"(a));
}

__device__ __forceinline__ float ex2f(float x) {
    float r;
    asm("ex2.approx.ftz.f32 %0, %1;" : "=f"(r) : "f"(x));
    return r;
}

__device__ __forceinline__ void cp16(unsigned s, const void* g) {
    asm volatile("cp.async.ca.shared.global [%0], [%1], 16;" :: "r"(s), "l"(g));
}

__device__ __forceinline__ unsigned smem_u32(const void* p) {
    return (unsigned)__cvta_generic_to_shared(p);
}

__device__ __forceinline__ unsigned pack_h2(float f0, float f1) {
    __half2 h = __floats2half2_rn(f0, f1);
    return *reinterpret_cast<unsigned*>(&h);
}

// ---------------------------------------------------------------------------
// Fused convert kernel: X -> g_xh, W -> g_wh (single fp16 each).
// ---------------------------------------------------------------------------
#define NX4 (NROWS * DMODEL / 4)
#define NW4 (E3 * DMODEL / 4)

__global__ void __launch_bounds__(256) convert_xw(const float* __restrict__ x,
                                                  const float* __restrict__ w) {
    int t = blockIdx.x * 256 + threadIdx.x;
    const float4 v = (t < NX4) ? reinterpret_cast<const float4*>(x)[t]
                               : reinterpret_cast<const float4*>(w)[t - NX4];
    uint2 o = make_uint2(pack_h2(v.x, v.y), pack_h2(v.z, v.w));
    if (t < NX4) reinterpret_cast<uint2*>(g_xh)[t] = o;
    else         reinterpret_cast<uint2*>(g_wh)[t - NX4] = o;
}

// ---------------------------------------------------------------------------
// Kernel 1: QKV projection GEMM (fp16 mma.sync + ldmatrix). Unchanged.
// ---------------------------------------------------------------------------
#define KPAD 40
#define ARR_B  (128 * KPAD * 2)
#define STG_B  (2 * ARR_B)
#define QKV_SMEM (3 * STG_B)

#define G_ISSUE(KT, ST)                                                               \
    do {                                                                              \
        const int _k0 = (KT) * 32;                                                    \
        _Pragma("unroll")                                                             \
        for (int _arr = 0; _arr < 2; _arr++) {                                        \
            _Pragma("unroll")                                                         \
            for (int _rep = 0; _rep < 2; _rep++) {                                    \
                int _sub = _rep * 256 + tid;                                          \
                int _row = _sub >> 2;                                                 \
                int _ch  = _sub & 3;                                                  \
                unsigned _sp = smem0 + (ST) * STG_B + _arr * ARR_B + _row * (KPAD*2) + _ch * 16; \
                const __half* _gp;                                                    \
                if (_arr == 0) _gp = g_xh + (size_t)(r0 + _row) * DMODEL + _k0 + _ch * 8; \
                else           _gp = g_wh + (size_t)(e0 + _row) * DMODEL + _k0 + _ch * 8; \
                cp16(_sp, _gp);                                                       \
            }                                                                         \
        }                                                                             \
        asm volatile("cp.async.commit_group;");                                       \
    } while (0)

__global__ void __launch_bounds__(256, 2) qkv_gemm_tc() {
    extern __shared__ __align__(16) char qsm[];
    const unsigned smem0 = smem_u32(qsm);

    const int tid   = threadIdx.x;
    const int wid   = tid >> 5;
    const int lane  = tid & 31;
    const int warpM = wid >> 1;
    const int warpN = wid & 1;
    const int r0    = blockIdx.y * 128;
    const int e0    = blockIdx.x * 128;

    const int fr = lane >> 2;
    const int fc = (lane & 3) * 2;

    const int lrA = lane & 15;
    const int lcA = (lane >> 4) << 3;
    const int lrB = (lane & 7) + ((lane >> 4) << 3);
    const int lcB = ((lane >> 3) & 1) << 3;

    float acc[2][8][4] = {};

    G_ISSUE(0, 0);
    G_ISSUE(1, 1);

    for (int kt = 0; kt < 32; kt++) {
        if (kt < 31) asm volatile("cp.async.wait_group 1;");
        else         asm volatile("cp.async.wait_group 0;");
        __syncthreads();
        if (kt + 2 < 32) G_ISSUE(kt + 2, (kt + 2) % 3);

        const int st = kt % 3;
        const unsigned uA = smem0 + st * STG_B;
        const unsigned uB = uA + ARR_B;

#pragma unroll
        for (int ks = 0; ks < 32; ks += 16) {
            unsigned ah[2][4], bh[4][4];
#pragma unroll
            for (int mf = 0; mf < 2; mf++) {
                const unsigned ao = (unsigned)(((warpM * 32 + mf * 16 + lrA) * KPAD + ks + lcA) * 2);
                ldm4(ah[mf], uA + ao);
            }
#pragma unroll
            for (int g4 = 0; g4 < 4; g4++) {
                const unsigned bo = (unsigned)(((warpN * 64 + g4 * 16 + lrB) * KPAD + ks + lcB) * 2);
                ldm4(bh[g4], uB + bo);
            }
#pragma unroll
            for (int mf = 0; mf < 2; mf++)
#pragma unroll
                for (int nf = 0; nf < 8; nf++) {
                    const unsigned* bf = &bh[nf >> 1][(nf & 1) * 2];
                    MMA_F16(acc[mf][nf], ah[mf], bf);
                }
        }
    }

#pragma unroll
    for (int mf = 0; mf < 2; mf++)
#pragma unroll
        for (int nf = 0; nf < 8; nf++) {
            const int row = r0 + warpM * 32 + mf * 16 + fr;
            const int col = e0 + warpN * 64 + nf * 8 + fc;
            *reinterpret_cast<float2*>(&g_qkv[(size_t)row * E3 + col]) =
                make_float2(acc[mf][nf][0], acc[mf][nf][1]);
            *reinterpret_cast<float2*>(&g_qkv[(size_t)(row + 8) * E3 + col]) =
                make_float2(acc[mf][nf][2], acc[mf][nf][3]);
        }
}

// ---------------------------------------------------------------------------
// Kernel 2 (fused prep): blocks [0, 8192): rope+convert Q/K.
//                        blocks [8192, 9216): V transpose+convert.
// ---------------------------------------------------------------------------
#define QSCALE 0.1803368801111243f   // 0.125 * log2(e)
#define QK_BLOCKS 8192

__global__ void __launch_bounds__(256) prep_qkv() {
    __shared__ float s[64][68];

    if (blockIdx.x < QK_BLOCKS) {
        const int t   = blockIdx.x * 256 + threadIdx.x;
        const int j   = t & 15;
        const int sqk = (t >> 4) & 1;
        const int h   = (t >> 5) & 15;
        const int r   = t >> 9;
        const int l   = r >> 1;
        const int b   = r & 1;

        const float* base = g_qkv + (size_t)r * E3 + h * 192 + sqk * 64;
        float x0 = base[j];
        float x1 = base[j + 16];
        float p0 = base[j + 32];
        float p1 = base[j + 48];

        float ang = (float)l * c_theta[j];
        float sn, cs;
        sincosf(ang, &sn, &cs);
        float y0 = x0 * cs - x1 * sn;
        float y1 = x1 * cs + x0 * sn;

        const size_t dst = ((size_t)(b * NHEADS + h) * L_SEQ + l) * DK;
        float vals[4] = {y0, y1, p0, p1};
        int   ds[4]   = {j, j + 16, j + 32, j + 48};

        if (sqk == 0) {
#pragma unroll
            for (int i = 0; i < 4; i++) {
                float v = vals[i] * QSCALE;
                __half hi = __float2half_rn(v);
                g_qhi[dst + ds[i]] = hi;
                g_qlo[dst + ds[i]] = __float2half_rn(v - __half2float(hi));
            }
        } else {
#pragma unroll
            for (int i = 0; i < 4; i++)
                g_kh[dst + ds[i]] = __float2half_rn(vals[i]);
        }
    } else {
        const int vb   = blockIdx.x - QK_BLOCKS;
        const int tile = vb & 31;
        const int h    = (vb >> 5) & 15;
        const int b    = vb >> 9;
        const int tid  = threadIdx.x;

#pragma unroll
        for (int i = 0; i < 4; i++) {
            int id  = i * 256 + tid;
            int row = id >> 4;
            int c4  = id & 15;
            const float* g = g_qkv + (size_t)((tile * 64 + row) * 2 + b) * E3 + h * 192 + 128 + c4 * 4;
            float4 v = *reinterpret_cast<const float4*>(g);
            s[row][c4 * 4 + 0] = v.x; s[row][c4 * 4 + 1] = v.y;
            s[row][c4 * 4 + 2] = v.z; s[row][c4 * 4 + 3] = v.w;
        }
        __syncthreads();

        const int d = tid & 63, part = tid >> 6;
        const size_t ob = ((size_t)(b * NHEADS + h) * DK + d) * L_SEQ + tile * 64 + part * 16;

#pragma unroll
        for (int kc = 0; kc < 2; kc++) {
            unsigned hw[4];
#pragma unroll
            for (int p = 0; p < 4; p++)
                hw[p] = pack_h2(s[part * 16 + kc * 8 + p * 2 + 0][d],
                                s[part * 16 + kc * 8 + p * 2 + 1][d]);
            *reinterpret_cast<uint4*>(g_vh + ob + kc * 8) = make_uint4(hw[0], hw[1], hw[2], hw[3]);
        }
    }
}

// ---------------------------------------------------------------------------
// Kernel 3: fp16 tensor-core flash attention.
// 256 threads = 8 warps x 16 query rows (128-query tile). 3-stage KV ring,
// single sync/tile. smem 92,160 B -> 2 CTAs/SM, 16 warps/SM.
// ---------------------------------------------------------------------------
#define ATTN_SMEM_BYTES ((18432 + 3 * 9216) * 2)   // 92160

__global__ void __launch_bounds__(256, 2) attn_tc(float* __restrict__ out) {
    extern __shared__ __align__(16) __half sm[];
    const unsigned smem_base = smem_u32(sm);

    const int tid  = threadIdx.x;
    const int w    = tid >> 5;          // 0..7
    const int lane = tid & 31;
    const int g    = lane >> 2;
    const int tg   = lane & 3;

    const int lrA = lane & 15;
    const int lcA = (lane >> 4) << 3;
    const int lrB = (lane & 7) + ((lane >> 4) << 3);
    const int lcB = ((lane >> 3) & 1) << 3;

    const int q0 = blockIdx.x * 128;
    const int h  = blockIdx.y;
    const int b  = blockIdx.z;
    const int hb = b * NHEADS + h;

    const size_t qkbase = (size_t)hb * L_SEQ * DK;
    const size_t vbase  = (size_t)hb * DK * L_SEQ;

    // Q tile loads: 128 rows x 8 chunks x {hi,lo} = 2048 cp16 over 256 threads
#pragma unroll
    for (int i = 0; i < 8; i++) {
        int id  = i * 256 + tid;
        int rid = (id >> 3) & 127;
        int ch  = id & 7;
        const __half* gp = (i < 4 ? g_qhi : g_qlo) + qkbase + (size_t)(q0 + rid) * DK + ch * 8;
        unsigned sp = smem_base + ((i < 4 ? 0 : 9216) + rid * 72 + ch * 8) * 2;
        cp16(sp, gp);
    }
    asm volatile("cp.async.commit_group;");

#define ISSUE_TILE(T, BUF)                                                            \
    do {                                                                              \
        _Pragma("unroll")                                                             \
        for (int i = 0; i < 4; i++) {                                                 \
            int id  = i * 256 + tid;                                                  \
            int arr = i >> 1;                                                         \
            int rid = (id >> 3) & 63;                                                 \
            int ch  = id & 7;                                                         \
            const __half* gp;                                                         \
            if (arr == 0) gp = g_kh + qkbase + (size_t)((T) * 64 + rid) * DK + ch * 8; \
            else          gp = g_vh + vbase + (size_t)rid * L_SEQ + (T) * 64 + ch * 8; \
            unsigned sp = smem_base + (18432 + (BUF) * 9216 + arr * 4608 + rid * 72 + ch * 8) * 2; \
            cp16(sp, gp);                                                             \
        }                                                                             \
        asm volatile("cp.async.commit_group;");                                       \
    } while (0)

    ISSUE_TILE(0, 0);
    ISSUE_TILE(1, 1);

    float o[8][4] = {};
    float mrow[2] = {-1e30f, -1e30f};
    float lrow[2] = {};

    const int rb0 = w * 16;   // warp's 16-row slice

    for (int t = 0; t < 32; t++) {
        if (t < 31) asm volatile("cp.async.wait_group 1;");
        else        asm volatile("cp.async.wait_group 0;");
        __syncthreads();
        if (t + 2 < 32) ISSUE_TILE(t + 2, (t + 2) % 3);

        const int st = t % 3;
        const unsigned uQh = smem_base;
        const unsigned uQl = smem_base + 9216 * 2;
        const unsigned uKh = smem_base + (18432 + st * 9216) * 2;
        const unsigned uVh = uKh + 4608 * 2;

        // ---- S = (Qhi + Qlo) Kh^T ----
        float s[8][4] = {};
#pragma unroll
        for (int kf = 0; kf < 4; kf++) {
            unsigned ah[4], al[4], kh[4][4];
            const unsigned ao = (unsigned)(((rb0 + lrA) * 72 + kf * 16 + lcA) * 2);
            ldm4(ah, uQh + ao);
            ldm4(al, uQl + ao);
#pragma unroll
            for (int g4 = 0; g4 < 4; g4++) {
                const unsigned bo = (unsigned)(((g4 * 16 + lrB) * 72 + kf * 16 + lcB) * 2);
                ldm4(kh[g4], uKh + bo);
            }
#pragma unroll
            for (int nf = 0; nf < 8; nf++) {
                const unsigned* bf = &kh[nf >> 1][(nf & 1) * 2];
                MMA_F16(s[nf], ah, bf);
                MMA_F16(s[nf], al, bf);
            }
        }

        // ---- online softmax (log2 domain) ----
        unsigned ph[4][4];
        {
            float mx0 = -1e30f, mx1 = -1e30f;
#pragma unroll
            for (int nf = 0; nf < 8; nf++) {
                mx0 = fmaxf(mx0, fmaxf(s[nf][0], s[nf][1]));
                mx1 = fmaxf(mx1, fmaxf(s[nf][2], s[nf][3]));
            }
            mx0 = fmaxf(mx0, __shfl_xor_sync(0xffffffffu, mx0, 1));
            mx0 = fmaxf(mx0, __shfl_xor_sync(0xffffffffu, mx0, 2));
            mx1 = fmaxf(mx1, __shfl_xor_sync(0xffffffffu, mx1, 1));
            mx1 = fmaxf(mx1, __shfl_xor_sync(0xffffffffu, mx1, 2));

            float mn0 = fmaxf(mrow[0], mx0);
            float mn1 = fmaxf(mrow[1], mx1);
            float sc0 = ex2f(mrow[0] - mn0);
            float sc1 = ex2f(mrow[1] - mn1);
            mrow[0] = mn0;
            mrow[1] = mn1;

            float rs0 = 0.f, rs1 = 0.f;
#pragma unroll
            for (int nf = 0; nf < 8; nf++) {
                s[nf][0] = ex2f(s[nf][0] - mn0);
                s[nf][1] = ex2f(s[nf][1] - mn0);
                s[nf][2] = ex2f(s[nf][2] - mn1);
                s[nf][3] = ex2f(s[nf][3] - mn1);
                rs0 += s[nf][0] + s[nf][1];
                rs1 += s[nf][2] + s[nf][3];
            }
            rs0 += __shfl_xor_sync(0xffffffffu, rs0, 1);
            rs0 += __shfl_xor_sync(0xffffffffu, rs0, 2);
            rs1 += __shfl_xor_sync(0xffffffffu, rs1, 1);
            rs1 += __shfl_xor_sync(0xffffffffu, rs1, 2);
            lrow[0] = lrow[0] * sc0 + rs0;
            lrow[1] = lrow[1] * sc1 + rs1;

#pragma unroll
            for (int nf = 0; nf < 8; nf++) {
                o[nf][0] *= sc0; o[nf][1] *= sc0;
                o[nf][2] *= sc1; o[nf][3] *= sc1;
            }

#pragma unroll
            for (int kf = 0; kf < 4; kf++) {
                const int n0 = 2 * kf, n1 = 2 * kf + 1;
                ph[kf][0] = pack_h2(s[n0][0], s[n0][1]);
                ph[kf][1] = pack_h2(s[n0][2], s[n0][3]);
                ph[kf][2] = pack_h2(s[n1][0], s[n1][1]);
                ph[kf][3] = pack_h2(s[n1][2], s[n1][3]);
            }
        }

        // ---- O += Ph Vh ----
#pragma unroll
        for (int kf = 0; kf < 4; kf++) {
            unsigned vh[4][4];
#pragma unroll
            for (int g4 = 0; g4 < 4; g4++) {
                const unsigned bo = (unsigned)(((g4 * 16 + lrB) * 72 + kf * 16 + lcB) * 2);
                ldm4(vh[g4], uVh + bo);
            }
#pragma unroll
            for (int nf = 0; nf < 8; nf++) {
                const unsigned* bf = &vh[nf >> 1][(nf & 1) * 2];
                MMA_F16(o[nf], ph[kf], bf);
            }
        }
    }

    // ---- epilogue: out[l][b][h*64 + d] ----
    {
        const float inv0 = 1.0f / lrow[0];
        const float inv1 = 1.0f / lrow[1];
        const int r0 = q0 + rb0 + g;
#pragma unroll
        for (int nf = 0; nf < 8; nf++) {
            const int col = h * 64 + nf * 8 + tg * 2;
            *reinterpret_cast<float2*>(out + (size_t)(r0 * 2 + b) * DMODEL + col) =
                make_float2(o[nf][0] * inv0, o[nf][1] * inv0);
            *reinterpret_cast<float2*>(out + (size_t)((r0 + 8) * 2 + b) * DMODEL + col) =
                make_float2(o[nf][2] * inv1, o[nf][3] * inv1);
        }
    }
}

// ---------------------------------------------------------------------------
extern "C" void kernel_launch(void* const* d_in, const int* in_sizes, int n_in,
                              void* d_out, int out_size) {
    const float* x = (const float*)d_in[0];
    const float* w = (const float*)d_in[1];
    if (n_in >= 2 && in_sizes[0] == E3 * DMODEL && in_sizes[1] == NROWS * DMODEL) {
        const float* t = x; x = w; w = t;
    }
    float* out = (float*)d_out;

    static bool attr_set = false;
    if (!attr_set) {
        cudaFuncSetAttribute(attn_tc, cudaFuncAttributeMaxDynamicSharedMemorySize,
                             ATTN_SMEM_BYTES);
        cudaFuncSetAttribute(qkv_gemm_tc, cudaFuncAttributeMaxDynamicSharedMemorySize,
                             QKV_SMEM);
        attr_set = true;
    }

    convert_xw<<<(NX4 + NW4) / 256, 256>>>(x, w);
    qkv_gemm_tc<<<dim3(E3 / 128, NROWS / 128), 256, QKV_SMEM>>>();
    prep_qkv<<<QK_BLOCKS + 1024, 256>>>();
    attn_tc<<<dim3(L_SEQ / 128, NHEADS, BATCH), 256, ATTN_SMEM_BYTES>>>(out);
}

// round 16
// speedup vs baseline: 1.0057x; 1.0057x over previous
#include <cuda_runtime.h>
#include <cuda_fp16.h>

#define L_SEQ  2048
#define BATCH  2
#define DMODEL 1024
#define NHEADS 16
#define DK     64
#define E3     3072
#define NROWS  4096

// fp32 QKV projection scratch: [NROWS][E3], row r = l*BATCH + b, col e = h*192 + {q,k,v}
__device__ float g_qkv[NROWS * E3];

// fp16 operands for the projection GEMM
__device__ __align__(16) __half g_xh[NROWS * DMODEL];
__device__ __align__(16) __half g_wh[E3 * DMODEL];

// Attention operands: Q hi/lo fp16 (rope + 0.125*log2e), K fp16 (rope), V fp16 [b][h][d][l].
#define QKV_ELEMS (BATCH * NHEADS * L_SEQ * DK)
__device__ __align__(16) __half g_qhi[QKV_ELEMS];
__device__ __align__(16) __half g_qlo[QKV_ELEMS];
__device__ __align__(16) __half g_kh [QKV_ELEMS];
__device__ __align__(16) __half g_vh [QKV_ELEMS];

__constant__ float c_theta[16] = {
    1.0f,                     0.5623413251903491f,     0.31622776601683794f,   0.17782794100389228f,
    0.1f,                     0.05623413251903491f,    0.031622776601683794f,  0.017782794100389228f,
    0.01f,                    0.005623413251903491f,   0.0031622776601683794f, 0.0017782794100389228f,
    0.001f,                   0.0005623413251903491f,  0.00031622776601683794f,0.00017782794100389227f
};

// ---------------------------------------------------------------------------
// Helpers
// ---------------------------------------------------------------------------
#define MMA_F16(C, A, B)                                                         \
    asm volatile("mma.sync.aligned.m16n8k16.row.col.f32.f16.f16.f32 "            \
                 "{%0,%1,%2,%3}, {%4,%5,%6,%7}, {%8,%9}, {%0,%1,%2,%3};"         \
                 : "+f"((C)[0]), "+f"((C)[1]), "+f"((C)[2]), "+f"((C)[3])        \
                 : "r"((A)[0]), "r"((A)[1]), "r"((A)[2]), "r"((A)[3]),           \
                   "r"((B)[0]), "r"((B)[1]))

__device__ __forceinline__ void ldm4(unsigned* r, unsigned a) {
    asm volatile("ldmatrix.sync.aligned.m8n8.x4.shared.b16 {%0,%1,%2,%3}, [%4];"
                 : "=r"(r[0]), "=r"(r[1]), "=r"(r[2]), "=r"(r[3]) : "r"(a));
}

__device__ __forceinline__ float ex2f(float x) {
    float r;
    asm("ex2.approx.ftz.f32 %0, %1;" : "=f"(r) : "f"(x));
    return r;
}

__device__ __forceinline__ void cp16(unsigned s, const void* g) {
    asm volatile("cp.async.ca.shared.global [%0], [%1], 16;" :: "r"(s), "l"(g));
}

__device__ __forceinline__ unsigned smem_u32(const void* p) {
    return (unsigned)__cvta_generic_to_shared(p);
}

__device__ __forceinline__ unsigned pack_h2(float f0, float f1) {
    __half2 h = __floats2half2_rn(f0, f1);
    return *reinterpret_cast<unsigned*>(&h);
}

// ---------------------------------------------------------------------------
// Fused convert kernel: X -> g_xh, W -> g_wh (single fp16 each).
// ---------------------------------------------------------------------------
#define NX4 (NROWS * DMODEL / 4)
#define NW4 (E3 * DMODEL / 4)

__global__ void __launch_bounds__(256) convert_xw(const float* __restrict__ x,
                                                  const float* __restrict__ w) {
    int t = blockIdx.x * 256 + threadIdx.x;
    const float4 v = (t < NX4) ? reinterpret_cast<const float4*>(x)[t]
                               : reinterpret_cast<const float4*>(w)[t - NX4];
    uint2 o = make_uint2(pack_h2(v.x, v.y), pack_h2(v.z, v.w));
    if (t < NX4) reinterpret_cast<uint2*>(g_xh)[t] = o;
    else         reinterpret_cast<uint2*>(g_wh)[t - NX4] = o;
}

// ---------------------------------------------------------------------------
// Kernel 1: QKV projection GEMM (fp16 mma.sync + ldmatrix). Unchanged.
// ---------------------------------------------------------------------------
#define KPAD 40
#define ARR_B  (128 * KPAD * 2)
#define STG_B  (2 * ARR_B)
#define QKV_SMEM (3 * STG_B)

#define G_ISSUE(KT, ST)                                                               \
    do {                                                                              \
        const int _k0 = (KT) * 32;                                                    \
        _Pragma("unroll")                                                             \
        for (int _arr = 0; _arr < 2; _arr++) {                                        \
            _Pragma("unroll")                                                         \
            for (int _rep = 0; _rep < 2; _rep++) {                                    \
                int _sub = _rep * 256 + tid;                                          \
                int _row = _sub >> 2;                                                 \
                int _ch  = _sub & 3;                                                  \
                unsigned _sp = smem0 + (ST) * STG_B + _arr * ARR_B + _row * (KPAD*2) + _ch * 16; \
                const __half* _gp;                                                    \
                if (_arr == 0) _gp = g_xh + (size_t)(r0 + _row) * DMODEL + _k0 + _ch * 8; \
                else           _gp = g_wh + (size_t)(e0 + _row) * DMODEL + _k0 + _ch * 8; \
                cp16(_sp, _gp);                                                       \
            }                                                                         \
        }                                                                             \
        asm volatile("cp.async.commit_group;");                                       \
    } while (0)

__global__ void __launch_bounds__(256, 2) qkv_gemm_tc() {
    extern __shared__ __align__(16) char qsm[];
    const unsigned smem0 = smem_u32(qsm);

    const int tid   = threadIdx.x;
    const int wid   = tid >> 5;
    const int lane  = tid & 31;
    const int warpM = wid >> 1;
    const int warpN = wid & 1;
    const int r0    = blockIdx.y * 128;
    const int e0    = blockIdx.x * 128;

    const int fr = lane >> 2;
    const int fc = (lane & 3) * 2;

    const int lrA = lane & 15;
    const int lcA = (lane >> 4) << 3;
    const int lrB = (lane & 7) + ((lane >> 4) << 3);
    const int lcB = ((lane >> 3) & 1) << 3;

    float acc[2][8][4] = {};

    G_ISSUE(0, 0);
    G_ISSUE(1, 1);

    for (int kt = 0; kt < 32; kt++) {
        if (kt < 31) asm volatile("cp.async.wait_group 1;");
        else         asm volatile("cp.async.wait_group 0;");
        __syncthreads();
        if (kt + 2 < 32) G_ISSUE(kt + 2, (kt + 2) % 3);

        const int st = kt % 3;
        const unsigned uA = smem0 + st * STG_B;
        const unsigned uB = uA + ARR_B;

#pragma unroll
        for (int ks = 0; ks < 32; ks += 16) {
            unsigned ah[2][4], bh[4][4];
#pragma unroll
            for (int mf = 0; mf < 2; mf++) {
                const unsigned ao = (unsigned)(((warpM * 32 + mf * 16 + lrA) * KPAD + ks + lcA) * 2);
                ldm4(ah[mf], uA + ao);
            }
#pragma unroll
            for (int g4 = 0; g4 < 4; g4++) {
                const unsigned bo = (unsigned)(((warpN * 64 + g4 * 16 + lrB) * KPAD + ks + lcB) * 2);
                ldm4(bh[g4], uB + bo);
            }
#pragma unroll
            for (int mf = 0; mf < 2; mf++)
#pragma unroll
                for (int nf = 0; nf < 8; nf++) {
                    const unsigned* bf = &bh[nf >> 1][(nf & 1) * 2];
                    MMA_F16(acc[mf][nf], ah[mf], bf);
                }
        }
    }

#pragma unroll
    for (int mf = 0; mf < 2; mf++)
#pragma unroll
        for (int nf = 0; nf < 8; nf++) {
            const int row = r0 + warpM * 32 + mf * 16 + fr;
            const int col = e0 + warpN * 64 + nf * 8 + fc;
            *reinterpret_cast<float2*>(&g_qkv[(size_t)row * E3 + col]) =
                make_float2(acc[mf][nf][0], acc[mf][nf][1]);
            *reinterpret_cast<float2*>(&g_qkv[(size_t)(row + 8) * E3 + col]) =
                make_float2(acc[mf][nf][2], acc[mf][nf][3]);
        }
}

// ---------------------------------------------------------------------------
// Kernel 2 (fused prep): blocks [0, 8192): rope+convert Q/K.
//                        blocks [8192, 9216): V transpose+convert.
// ---------------------------------------------------------------------------
#define QSCALE 0.1803368801111243f   // 0.125 * log2(e)
#define QK_BLOCKS 8192

__global__ void __launch_bounds__(256) prep_qkv() {
    __shared__ float s[64][68];

    if (blockIdx.x < QK_BLOCKS) {
        const int t   = blockIdx.x * 256 + threadIdx.x;
        const int j   = t & 15;
        const int sqk = (t >> 4) & 1;
        const int h   = (t >> 5) & 15;
        const int r   = t >> 9;
        const int l   = r >> 1;
        const int b   = r & 1;

        const float* base = g_qkv + (size_t)r * E3 + h * 192 + sqk * 64;
        float x0 = base[j];
        float x1 = base[j + 16];
        float p0 = base[j + 32];
        float p1 = base[j + 48];

        float ang = (float)l * c_theta[j];
        float sn, cs;
        sincosf(ang, &sn, &cs);
        float y0 = x0 * cs - x1 * sn;
        float y1 = x1 * cs + x0 * sn;

        const size_t dst = ((size_t)(b * NHEADS + h) * L_SEQ + l) * DK;
        float vals[4] = {y0, y1, p0, p1};
        int   ds[4]   = {j, j + 16, j + 32, j + 48};

        if (sqk == 0) {
#pragma unroll
            for (int i = 0; i < 4; i++) {
                float v = vals[i] * QSCALE;
                __half hi = __float2half_rn(v);
                g_qhi[dst + ds[i]] = hi;
                g_qlo[dst + ds[i]] = __float2half_rn(v - __half2float(hi));
            }
        } else {
#pragma unroll
            for (int i = 0; i < 4; i++)
                g_kh[dst + ds[i]] = __float2half_rn(vals[i]);
        }
    } else {
        const int vb   = blockIdx.x - QK_BLOCKS;
        const int tile = vb & 31;
        const int h    = (vb >> 5) & 15;
        const int b    = vb >> 9;
        const int tid  = threadIdx.x;

#pragma unroll
        for (int i = 0; i < 4; i++) {
            int id  = i * 256 + tid;
            int row = id >> 4;
            int c4  = id & 15;
            const float* g = g_qkv + (size_t)((tile * 64 + row) * 2 + b) * E3 + h * 192 + 128 + c4 * 4;
            float4 v = *reinterpret_cast<const float4*>(g);
            s[row][c4 * 4 + 0] = v.x; s[row][c4 * 4 + 1] = v.y;
            s[row][c4 * 4 + 2] = v.z; s[row][c4 * 4 + 3] = v.w;
        }
        __syncthreads();

        const int d = tid & 63, part = tid >> 6;
        const size_t ob = ((size_t)(b * NHEADS + h) * DK + d) * L_SEQ + tile * 64 + part * 16;

#pragma unroll
        for (int kc = 0; kc < 2; kc++) {
            unsigned hw[4];
#pragma unroll
            for (int p = 0; p < 4; p++)
                hw[p] = pack_h2(s[part * 16 + kc * 8 + p * 2 + 0][d],
                                s[part * 16 + kc * 8 + p * 2 + 1][d]);
            *reinterpret_cast<uint4*>(g_vh + ob + kc * 8) = make_uint4(hw[0], hw[1], hw[2], hw[3]);
        }
    }
}

// ---------------------------------------------------------------------------
// Kernel 3: fp16 flash attention, two-tile software pipeline.
// 256 threads = 8 warps x 16 query rows. KV tiles processed in PAIRS:
// S_a, S_b MMA batches up-front; PV_a (tensor) overlaps softmax_b (ALU/SHFL).
// 4-stage KV ring, one sync per pair. smem: Q 36,864 + 4 x 18,432 = 110,592 B.
// ---------------------------------------------------------------------------
#define ATTN_SMem_STAGE 9216
#define ATTN_SMEM_BYTES ((18432 + 4 * 9216) * 2)   // 110592

__global__ void __launch_bounds__(256, 1) attn_tc(float* __restrict__ out) {
    extern __shared__ __align__(16) __half sm[];
    const unsigned smem_base = smem_u32(sm);

    const int tid  = threadIdx.x;
    const int w    = tid >> 5;          // 0..7
    const int lane = tid & 31;
    const int g    = lane >> 2;
    const int tg   = lane & 3;

    const int lrA = lane & 15;
    const int lcA = (lane >> 4) << 3;
    const int lrB = (lane & 7) + ((lane >> 4) << 3);
    const int lcB = ((lane >> 3) & 1) << 3;

    const int q0 = blockIdx.x * 128;
    const int h  = blockIdx.y;
    const int b  = blockIdx.z;
    const int hb = b * NHEADS + h;

    const size_t qkbase = (size_t)hb * L_SEQ * DK;
    const size_t vbase  = (size_t)hb * DK * L_SEQ;

    // Q tile loads
#pragma unroll
    for (int i = 0; i < 8; i++) {
        int id  = i * 256 + tid;
        int rid = (id >> 3) & 127;
        int ch  = id & 7;
        const __half* gp = (i < 4 ? g_qhi : g_qlo) + qkbase + (size_t)(q0 + rid) * DK + ch * 8;
        unsigned sp = smem_base + ((i < 4 ? 0 : 9216) + rid * 72 + ch * 8) * 2;
        cp16(sp, gp);
    }
    asm volatile("cp.async.commit_group;");

#define ISSUE_TILE(T, BUF)                                                            \
    do {                                                                              \
        _Pragma("unroll")                                                             \
        for (int i = 0; i < 4; i++) {                                                 \
            int id  = i * 256 + tid;                                                  \
            int arr = i >> 1;                                                         \
            int rid = (id >> 3) & 63;                                                 \
            int ch  = id & 7;                                                         \
            const __half* gp;                                                         \
            if (arr == 0) gp = g_kh + qkbase + (size_t)((T) * 64 + rid) * DK + ch * 8; \
            else          gp = g_vh + vbase + (size_t)rid * L_SEQ + (T) * 64 + ch * 8; \
            unsigned sp = smem_base + (18432 + (BUF) * 9216 + arr * 4608 + rid * 72 + ch * 8) * 2; \
            cp16(sp, gp);                                                             \
        }                                                                             \
        asm volatile("cp.async.commit_group;");                                       \
    } while (0)

    ISSUE_TILE(0, 0);
    ISSUE_TILE(1, 1);

    float o[8][4] = {};
    float mrow[2] = {-1e30f, -1e30f};
    float lrow[2] = {};

    const int rb0 = w * 16;

    // Online softmax for one S tile: updates mrow/lrow, rescales o, packs P.
#define SOFTMAX_PACK(S, PH)                                                           \
    do {                                                                              \
        float mx0 = -1e30f, mx1 = -1e30f;                                             \
        _Pragma("unroll")                                                             \
        for (int nf = 0; nf < 8; nf++) {                                              \
            mx0 = fmaxf(mx0, fmaxf((S)[nf][0], (S)[nf][1]));                          \
            mx1 = fmaxf(mx1, fmaxf((S)[nf][2], (S)[nf][3]));                          \
        }                                                                             \
        mx0 = fmaxf(mx0, __shfl_xor_sync(0xffffffffu, mx0, 1));                       \
        mx0 = fmaxf(mx0, __shfl_xor_sync(0xffffffffu, mx0, 2));                       \
        mx1 = fmaxf(mx1, __shfl_xor_sync(0xffffffffu, mx1, 1));                       \
        mx1 = fmaxf(mx1, __shfl_xor_sync(0xffffffffu, mx1, 2));                       \
        float mn0 = fmaxf(mrow[0], mx0);                                              \
        float mn1 = fmaxf(mrow[1], mx1);                                              \
        float sc0 = ex2f(mrow[0] - mn0);                                              \
        float sc1 = ex2f(mrow[1] - mn1);                                              \
        mrow[0] = mn0;                                                                \
        mrow[1] = mn1;                                                                \
        float rs0 = 0.f, rs1 = 0.f;                                                   \
        _Pragma("unroll")                                                             \
        for (int nf = 0; nf < 8; nf++) {                                              \
            (S)[nf][0] = ex2f((S)[nf][0] - mn0);                                      \
            (S)[nf][1] = ex2f((S)[nf][1] - mn0);                                      \
            (S)[nf][2] = ex2f((S)[nf][2] - mn1);                                      \
            (S)[nf][3] = ex2f((S)[nf][3] - mn1);                                      \
            rs0 += (S)[nf][0] + (S)[nf][1];                                           \
            rs1 += (S)[nf][2] + (S)[nf][3];                                           \
        }                                                                             \
        rs0 += __shfl_xor_sync(0xffffffffu, rs0, 1);                                  \
        rs0 += __shfl_xor_sync(0xffffffffu, rs0, 2);                                  \
        rs1 += __shfl_xor_sync(0xffffffffu, rs1, 1);                                  \
        rs1 += __shfl_xor_sync(0xffffffffu, rs1, 2);                                  \
        lrow[0] = lrow[0] * sc0 + rs0;                                                \
        lrow[1] = lrow[1] * sc1 + rs1;                                                \
        _Pragma("unroll")                                                             \
        for (int nf = 0; nf < 8; nf++) {                                              \
            o[nf][0] *= sc0; o[nf][1] *= sc0;                                         \
            o[nf][2] *= sc1; o[nf][3] *= sc1;                                         \
        }                                                                             \
        _Pragma("unroll")                                                             \
        for (int kf = 0; kf < 4; kf++) {                                              \
            const int n0 = 2 * kf, n1 = 2 * kf + 1;                                   \
            (PH)[kf][0] = pack_h2((S)[n0][0], (S)[n0][1]);                            \
            (PH)[kf][1] = pack_h2((S)[n0][2], (S)[n0][3]);                            \
            (PH)[kf][2] = pack_h2((S)[n1][0], (S)[n1][1]);                            \
            (PH)[kf][3] = pack_h2((S)[n1][2], (S)[n1][3]);                            \
        }                                                                             \
    } while (0)

    // S = (Qhi + Qlo) Kh^T for one stage.
#define QK_MMA(S, UK)                                                                 \
    do {                                                                              \
        _Pragma("unroll")                                                             \
        for (int kf = 0; kf < 4; kf++) {                                              \
            unsigned ah[4], al[4], kh[4][4];                                          \
            const unsigned ao = (unsigned)(((rb0 + lrA) * 72 + kf * 16 + lcA) * 2);   \
            ldm4(ah, uQh + ao);                                                       \
            ldm4(al, uQl + ao);                                                       \
            _Pragma("unroll")                                                         \
            for (int g4 = 0; g4 < 4; g4++) {                                          \
                const unsigned bo = (unsigned)(((g4 * 16 + lrB) * 72 + kf * 16 + lcB) * 2); \
                ldm4(kh[g4], (UK) + bo);                                              \
            }                                                                         \
            _Pragma("unroll")                                                         \
            for (int nf = 0; nf < 8; nf++) {                                          \
                const unsigned* bf = &kh[nf >> 1][(nf & 1) * 2];                      \
                MMA_F16((S)[nf], ah, bf);                                             \
                MMA_F16((S)[nf], al, bf);                                             \
            }                                                                         \
        }                                                                             \
    } while (0)

    // O += Ph Vh for one stage.
#define PV_MMA(PH, UV)                                                                \
    do {                                                                              \
        _Pragma("unroll")                                                             \
        for (int kf = 0; kf < 4; kf++) {                                              \
            unsigned vh[4][4];                                                        \
            _Pragma("unroll")                                                         \
            for (int g4 = 0; g4 < 4; g4++) {                                          \
                const unsigned bo = (unsigned)(((g4 * 16 + lrB) * 72 + kf * 16 + lcB) * 2); \
                ldm4(vh[g4], (UV) + bo);                                              \
            }                                                                         \
            _Pragma("unroll")                                                         \
            for (int nf = 0; nf < 8; nf++) {                                          \
                const unsigned* bf = &vh[nf >> 1][(nf & 1) * 2];                      \
                MMA_F16(o[nf], (PH)[kf], bf);                                         \
            }                                                                         \
        }                                                                             \
    } while (0)

    const unsigned uQh = smem_base;
    const unsigned uQl = smem_base + 9216 * 2;

    for (int t = 0; t < 32; t += 2) {
        asm volatile("cp.async.wait_group 0;");
        __syncthreads();
        if (t + 2 < 32) {
            ISSUE_TILE(t + 2, (t + 2) & 3);
            ISSUE_TILE(t + 3, (t + 3) & 3);
        }

        const unsigned uKa = smem_base + (18432 + (t & 3) * 9216) * 2;
        const unsigned uVa = uKa + 4608 * 2;
        const unsigned uKb = smem_base + (18432 + ((t + 1) & 3) * 9216) * 2;
        const unsigned uVb = uKb + 4608 * 2;

        // Batch both QK tile MMAs up-front.
        float sa[8][4] = {};
        float sb[8][4] = {};
        QK_MMA(sa, uKa);
        QK_MMA(sb, uKb);

        // softmax_a ; then PV_a (tensor) overlaps softmax_b (ALU/SHFL/MUFU).
        unsigned ph[4][4];
        SOFTMAX_PACK(sa, ph);
        PV_MMA(ph, uVa);
        SOFTMAX_PACK(sb, ph);
        PV_MMA(ph, uVb);
    }

    // ---- epilogue: out[l][b][h*64 + d] ----
    {
        const float inv0 = 1.0f / lrow[0];
        const float inv1 = 1.0f / lrow[1];
        const int r0 = q0 + rb0 + g;
#pragma unroll
        for (int nf = 0; nf < 8; nf++) {
            const int col = h * 64 + nf * 8 + tg * 2;
            *reinterpret_cast<float2*>(out + (size_t)(r0 * 2 + b) * DMODEL + col) =
                make_float2(o[nf][0] * inv0, o[nf][1] * inv0);
            *reinterpret_cast<float2*>(out + (size_t)((r0 + 8) * 2 + b) * DMODEL + col) =
                make_float2(o[nf][2] * inv1, o[nf][3] * inv1);
        }
    }
}

// ---------------------------------------------------------------------------
extern "C" void kernel_launch(void* const* d_in, const int* in_sizes, int n_in,
                              void* d_out, int out_size) {
    const float* x = (const float*)d_in[0];
    const float* w = (const float*)d_in[1];
    if (n_in >= 2 && in_sizes[0] == E3 * DMODEL && in_sizes[1] == NROWS * DMODEL) {
        const float* t = x; x = w; w = t;
    }
    float* out = (float*)d_out;

    static bool attr_set = false;
    if (!attr_set) {
        cudaFuncSetAttribute(attn_tc, cudaFuncAttributeMaxDynamicSharedMemorySize,
                             ATTN_SMEM_BYTES);
        cudaFuncSetAttribute(qkv_gemm_tc, cudaFuncAttributeMaxDynamicSharedMemorySize,
                             QKV_SMEM);
        attr_set = true;
    }

    convert_xw<<<(NX4 + NW4) / 256, 256>>>(x, w);
    qkv_gemm_tc<<<dim3(E3 / 128, NROWS / 128), 256, QKV_SMEM>>>();
    prep_qkv<<<QK_BLOCKS + 1024, 256>>>();
    attn_tc<<<dim3(L_SEQ / 128, NHEADS, BATCH), 256, ATTN_SMEM_BYTES>>>(out);
}

// round 17
// speedup vs baseline: 1.1744x; 1.1677x over previous
#include <cuda_runtime.h>
#include <cuda_fp16.h>

#define L_SEQ  2048
#define BATCH  2
#define DMODEL 1024
#define NHEADS 16
#define DK     64
#define E3     3072
#define NROWS  4096

// fp32 QKV projection scratch: [NROWS][E3], row r = l*BATCH + b, col e = h*192 + {q,k,v}
__device__ float g_qkv[NROWS * E3];

// fp16 operands for the projection GEMM
__device__ __align__(16) __half g_xh[NROWS * DMODEL];
__device__ __align__(16) __half g_wh[E3 * DMODEL];

// Attention operands (all single fp16): Q (rope + 0.125*log2e), K (rope), V [b][h][d][l].
#define QKV_ELEMS (BATCH * NHEADS * L_SEQ * DK)
__device__ __align__(16) __half g_qh[QKV_ELEMS];
__device__ __align__(16) __half g_kh[QKV_ELEMS];
__device__ __align__(16) __half g_vh[QKV_ELEMS];

__constant__ float c_theta[16] = {
    1.0f,                     0.5623413251903491f,     0.31622776601683794f,   0.17782794100389228f,
    0.1f,                     0.05623413251903491f,    0.031622776601683794f,  0.017782794100389228f,
    0.01f,                    0.005623413251903491f,   0.0031622776601683794f, 0.0017782794100389228f,
    0.001f,                   0.0005623413251903491f,  0.00031622776601683794f,0.00017782794100389227f
};

// ---------------------------------------------------------------------------
// Helpers
// ---------------------------------------------------------------------------
#define MMA_F16(C, A, B)                                                         \
    asm volatile("mma.sync.aligned.m16n8k16.row.col.f32.f16.f16.f32 "            \
                 "{%0,%1,%2,%3}, {%4,%5,%6,%7}, {%8,%9}, {%0,%1,%2,%3};"         \
                 : "+f"((C)[0]), "+f"((C)[1]), "+f"((C)[2]), "+f"((C)[3])        \
                 : "r"((A)[0]), "r"((A)[1]), "r"((A)[2]), "r"((A)[3]),           \
                   "r"((B)[0]), "r"((B)[1]))

__device__ __forceinline__ void ldm4(unsigned* r, unsigned a) {
    asm volatile("ldmatrix.sync.aligned.m8n8.x4.shared.b16 {%0,%1,%2,%3}, [%4];"
                 : "=r"(r[0]), "=r"(r[1]), "=r"(r[2]), "=r"(r[3]) : "r"(a));
}

__device__ __forceinline__ float ex2f(float x) {
    float r;
    asm("ex2.approx.ftz.f32 %0, %1;" : "=f"(r) : "f"(x));
    return r;
}

__device__ __forceinline__ void cp16(unsigned s, const void* g) {
    asm volatile("cp.async.ca.shared.global [%0], [%1], 16;" :: "r"(s), "l"(g));
}

__device__ __forceinline__ unsigned smem_u32(const void* p) {
    return (unsigned)__cvta_generic_to_shared(p);
}

__device__ __forceinline__ unsigned pack_h2(float f0, float f1) {
    __half2 h = __floats2half2_rn(f0, f1);
    return *reinterpret_cast<unsigned*>(&h);
}

// ---------------------------------------------------------------------------
// Fused convert kernel: X -> g_xh, W -> g_wh (single fp16 each).
// ---------------------------------------------------------------------------
#define NX4 (NROWS * DMODEL / 4)
#define NW4 (E3 * DMODEL / 4)

__global__ void __launch_bounds__(256) convert_xw(const float* __restrict__ x,
                                                  const float* __restrict__ w) {
    int t = blockIdx.x * 256 + threadIdx.x;
    const float4 v = (t < NX4) ? reinterpret_cast<const float4*>(x)[t]
                               : reinterpret_cast<const float4*>(w)[t - NX4];
    uint2 o = make_uint2(pack_h2(v.x, v.y), pack_h2(v.z, v.w));
    if (t < NX4) reinterpret_cast<uint2*>(g_xh)[t] = o;
    else         reinterpret_cast<uint2*>(g_wh)[t - NX4] = o;
}

// ---------------------------------------------------------------------------
// Kernel 1: QKV projection GEMM (fp16 mma.sync + ldmatrix). Unchanged from R14.
// ---------------------------------------------------------------------------
#define KPAD 40
#define ARR_B  (128 * KPAD * 2)
#define STG_B  (2 * ARR_B)
#define QKV_SMEM (3 * STG_B)

#define G_ISSUE(KT, ST)                                                               \
    do {                                                                              \
        const int _k0 = (KT) * 32;                                                    \
        _Pragma("unroll")                                                             \
        for (int _arr = 0; _arr < 2; _arr++) {                                        \
            _Pragma("unroll")                                                         \
            for (int _rep = 0; _rep < 2; _rep++) {                                    \
                int _sub = _rep * 256 + tid;                                          \
                int _row = _sub >> 2;                                                 \
                int _ch  = _sub & 3;                                                  \
                unsigned _sp = smem0 + (ST) * STG_B + _arr * ARR_B + _row * (KPAD*2) + _ch * 16; \
                const __half* _gp;                                                    \
                if (_arr == 0) _gp = g_xh + (size_t)(r0 + _row) * DMODEL + _k0 + _ch * 8; \
                else           _gp = g_wh + (size_t)(e0 + _row) * DMODEL + _k0 + _ch * 8; \
                cp16(_sp, _gp);                                                       \
            }                                                                         \
        }                                                                             \
        asm volatile("cp.async.commit_group;");                                       \
    } while (0)

__global__ void __launch_bounds__(256, 2) qkv_gemm_tc() {
    extern __shared__ __align__(16) char qsm[];
    const unsigned smem0 = smem_u32(qsm);

    const int tid   = threadIdx.x;
    const int wid   = tid >> 5;
    const int lane  = tid & 31;
    const int warpM = wid >> 1;
    const int warpN = wid & 1;
    const int r0    = blockIdx.y * 128;
    const int e0    = blockIdx.x * 128;

    const int fr = lane >> 2;
    const int fc = (lane & 3) * 2;

    const int lrA = lane & 15;
    const int lcA = (lane >> 4) << 3;
    const int lrB = (lane & 7) + ((lane >> 4) << 3);
    const int lcB = ((lane >> 3) & 1) << 3;

    float acc[2][8][4] = {};

    G_ISSUE(0, 0);
    G_ISSUE(1, 1);

    for (int kt = 0; kt < 32; kt++) {
        if (kt < 31) asm volatile("cp.async.wait_group 1;");
        else         asm volatile("cp.async.wait_group 0;");
        __syncthreads();
        if (kt + 2 < 32) G_ISSUE(kt + 2, (kt + 2) % 3);

        const int st = kt % 3;
        const unsigned uA = smem0 + st * STG_B;
        const unsigned uB = uA + ARR_B;

#pragma unroll
        for (int ks = 0; ks < 32; ks += 16) {
            unsigned ah[2][4], bh[4][4];
#pragma unroll
            for (int mf = 0; mf < 2; mf++) {
                const unsigned ao = (unsigned)(((warpM * 32 + mf * 16 + lrA) * KPAD + ks + lcA) * 2);
                ldm4(ah[mf], uA + ao);
            }
#pragma unroll
            for (int g4 = 0; g4 < 4; g4++) {
                const unsigned bo = (unsigned)(((warpN * 64 + g4 * 16 + lrB) * KPAD + ks + lcB) * 2);
                ldm4(bh[g4], uB + bo);
            }
#pragma unroll
            for (int mf = 0; mf < 2; mf++)
#pragma unroll
                for (int nf = 0; nf < 8; nf++) {
                    const unsigned* bf = &bh[nf >> 1][(nf & 1) * 2];
                    MMA_F16(acc[mf][nf], ah[mf], bf);
                }
        }
    }

#pragma unroll
    for (int mf = 0; mf < 2; mf++)
#pragma unroll
        for (int nf = 0; nf < 8; nf++) {
            const int row = r0 + warpM * 32 + mf * 16 + fr;
            const int col = e0 + warpN * 64 + nf * 8 + fc;
            *reinterpret_cast<float2*>(&g_qkv[(size_t)row * E3 + col]) =
                make_float2(acc[mf][nf][0], acc[mf][nf][1]);
            *reinterpret_cast<float2*>(&g_qkv[(size_t)(row + 8) * E3 + col]) =
                make_float2(acc[mf][nf][2], acc[mf][nf][3]);
        }
}

// ---------------------------------------------------------------------------
// Kernel 2 (fused prep): blocks [0, 8192): rope+convert Q/K (single fp16 each).
//                        blocks [8192, 9216): V transpose+convert.
// ---------------------------------------------------------------------------
#define QSCALE 0.1803368801111243f   // 0.125 * log2(e)
#define QK_BLOCKS 8192

__global__ void __launch_bounds__(256) prep_qkv() {
    __shared__ float s[64][68];

    if (blockIdx.x < QK_BLOCKS) {
        const int t   = blockIdx.x * 256 + threadIdx.x;
        const int j   = t & 15;
        const int sqk = (t >> 4) & 1;
        const int h   = (t >> 5) & 15;
        const int r   = t >> 9;
        const int l   = r >> 1;
        const int b   = r & 1;

        const float* base = g_qkv + (size_t)r * E3 + h * 192 + sqk * 64;
        float x0 = base[j];
        float x1 = base[j + 16];
        float p0 = base[j + 32];
        float p1 = base[j + 48];

        float ang = (float)l * c_theta[j];
        float sn, cs;
        sincosf(ang, &sn, &cs);
        float y0 = x0 * cs - x1 * sn;
        float y1 = x1 * cs + x0 * sn;

        const size_t dst = ((size_t)(b * NHEADS + h) * L_SEQ + l) * DK;
        const float sc = sqk ? 1.0f : QSCALE;
        __half* dh = (sqk ? g_kh : g_qh) + dst;
        dh[j]      = __float2half_rn(y0 * sc);
        dh[j + 16] = __float2half_rn(y1 * sc);
        dh[j + 32] = __float2half_rn(p0 * sc);
        dh[j + 48] = __float2half_rn(p1 * sc);
    } else {
        const int vb   = blockIdx.x - QK_BLOCKS;
        const int tile = vb & 31;
        const int h    = (vb >> 5) & 15;
        const int b    = vb >> 9;
        const int tid  = threadIdx.x;

#pragma unroll
        for (int i = 0; i < 4; i++) {
            int id  = i * 256 + tid;
            int row = id >> 4;
            int c4  = id & 15;
            const float* g = g_qkv + (size_t)((tile * 64 + row) * 2 + b) * E3 + h * 192 + 128 + c4 * 4;
            float4 v = *reinterpret_cast<const float4*>(g);
            s[row][c4 * 4 + 0] = v.x; s[row][c4 * 4 + 1] = v.y;
            s[row][c4 * 4 + 2] = v.z; s[row][c4 * 4 + 3] = v.w;
        }
        __syncthreads();

        const int d = tid & 63, part = tid >> 6;
        const size_t ob = ((size_t)(b * NHEADS + h) * DK + d) * L_SEQ + tile * 64 + part * 16;

#pragma unroll
        for (int kc = 0; kc < 2; kc++) {
            unsigned hw[4];
#pragma unroll
            for (int p = 0; p < 4; p++)
                hw[p] = pack_h2(s[part * 16 + kc * 8 + p * 2 + 0][d],
                                s[part * 16 + kc * 8 + p * 2 + 1][d]);
            *reinterpret_cast<uint4*>(g_vh + ob + kc * 8) = make_uint4(hw[0], hw[1], hw[2], hw[3]);
        }
    }
}

// ---------------------------------------------------------------------------
// Kernel 3: fp16 flash attention (single-precision Q, K, V, P).
// S = Qh Kh^T (1 MMA) ; O += Ph Vh (1 MMA).
// 128 threads = 4 warps x 32 query rows (2 m-frags). 3-stage KV ring,
// single sync/tile. smem: Q 18,432 + 3 x 18,432 = 73,728 B -> 2 CTAs/SM.
// ---------------------------------------------------------------------------
#define ATTN_SMEM_BYTES ((9216 + 3 * 9216) * 2)   // 73728

__global__ void __launch_bounds__(128, 2) attn_tc(float* __restrict__ out) {
    extern __shared__ __align__(16) __half sm[];
    const unsigned smem_base = smem_u32(sm);

    const int tid  = threadIdx.x;
    const int w    = tid >> 5;
    const int lane = tid & 31;
    const int g    = lane >> 2;
    const int tg   = lane & 3;

    const int lrA = lane & 15;
    const int lcA = (lane >> 4) << 3;
    const int lrB = (lane & 7) + ((lane >> 4) << 3);
    const int lcB = ((lane >> 3) & 1) << 3;

    const int q0 = blockIdx.x * 128;
    const int h  = blockIdx.y;
    const int b  = blockIdx.z;
    const int hb = b * NHEADS + h;

    const size_t qkbase = (size_t)hb * L_SEQ * DK;
    const size_t vbase  = (size_t)hb * DK * L_SEQ;

    // Q tile: 128 rows x 8 chunks = 1024 cp16 over 128 threads
#pragma unroll
    for (int i = 0; i < 8; i++) {
        int id  = i * 128 + tid;
        int rid = (id >> 3) & 127;
        int ch  = id & 7;
        const __half* gp = g_qh + qkbase + (size_t)(q0 + rid) * DK + ch * 8;
        unsigned sp = smem_base + (rid * 72 + ch * 8) * 2;
        cp16(sp, gp);
    }
    asm volatile("cp.async.commit_group;");

#define ISSUE_TILE(T, BUF)                                                            \
    do {                                                                              \
        _Pragma("unroll")                                                             \
        for (int i = 0; i < 8; i++) {                                                 \
            int id  = i * 128 + tid;                                                  \
            int arr = i >> 2;                                                         \
            int rid = (id >> 3) & 63;                                                 \
            int ch  = id & 7;                                                         \
            const __half* gp;                                                         \
            if (arr == 0) gp = g_kh + qkbase + (size_t)((T) * 64 + rid) * DK + ch * 8; \
            else          gp = g_vh + vbase + (size_t)rid * L_SEQ + (T) * 64 + ch * 8; \
            unsigned sp = smem_base + (9216 + (BUF) * 9216 + arr * 4608 + rid * 72 + ch * 8) * 2; \
            cp16(sp, gp);                                                             \
        }                                                                             \
        asm volatile("cp.async.commit_group;");                                       \
    } while (0)

    ISSUE_TILE(0, 0);
    ISSUE_TILE(1, 1);

    float o[2][8][4] = {};
    float mrow[2][2] = {{-1e30f, -1e30f}, {-1e30f, -1e30f}};
    float lrow[2][2] = {};

    const int rb0 = w * 32;

    for (int t = 0; t < 32; t++) {
        if (t < 31) asm volatile("cp.async.wait_group 1;");
        else        asm volatile("cp.async.wait_group 0;");
        __syncthreads();
        if (t + 2 < 32) ISSUE_TILE(t + 2, (t + 2) % 3);

        const int st = t % 3;
        const unsigned uQh = smem_base;
        const unsigned uKh = smem_base + (9216 + st * 9216) * 2;
        const unsigned uVh = uKh + 4608 * 2;

        // ---- S = Qh Kh^T ----
        float s[2][8][4] = {};
#pragma unroll
        for (int kf = 0; kf < 4; kf++) {
            unsigned ah[2][4], kh[4][4];
#pragma unroll
            for (int mf = 0; mf < 2; mf++) {
                const unsigned ao = (unsigned)(((rb0 + mf * 16 + lrA) * 72 + kf * 16 + lcA) * 2);
                ldm4(ah[mf], uQh + ao);
            }
#pragma unroll
            for (int g4 = 0; g4 < 4; g4++) {
                const unsigned bo = (unsigned)(((g4 * 16 + lrB) * 72 + kf * 16 + lcB) * 2);
                ldm4(kh[g4], uKh + bo);
            }
#pragma unroll
            for (int nf = 0; nf < 8; nf++) {
                const unsigned* bf = &kh[nf >> 1][(nf & 1) * 2];
#pragma unroll
                for (int mf = 0; mf < 2; mf++)
                    MMA_F16(s[mf][nf], ah[mf], bf);
            }
        }

        // ---- online softmax (log2 domain) ----
        unsigned ph[2][4][4];
#pragma unroll
        for (int mf = 0; mf < 2; mf++) {
            float mx0 = -1e30f, mx1 = -1e30f;
#pragma unroll
            for (int nf = 0; nf < 8; nf++) {
                mx0 = fmaxf(mx0, fmaxf(s[mf][nf][0], s[mf][nf][1]));
                mx1 = fmaxf(mx1, fmaxf(s[mf][nf][2], s[mf][nf][3]));
            }
            mx0 = fmaxf(mx0, __shfl_xor_sync(0xffffffffu, mx0, 1));
            mx0 = fmaxf(mx0, __shfl_xor_sync(0xffffffffu, mx0, 2));
            mx1 = fmaxf(mx1, __shfl_xor_sync(0xffffffffu, mx1, 1));
            mx1 = fmaxf(mx1, __shfl_xor_sync(0xffffffffu, mx1, 2));

            float mn0 = fmaxf(mrow[mf][0], mx0);
            float mn1 = fmaxf(mrow[mf][1], mx1);
            float sc0 = ex2f(mrow[mf][0] - mn0);
            float sc1 = ex2f(mrow[mf][1] - mn1);
            mrow[mf][0] = mn0;
            mrow[mf][1] = mn1;

            float rs0 = 0.f, rs1 = 0.f;
#pragma unroll
            for (int nf = 0; nf < 8; nf++) {
                s[mf][nf][0] = ex2f(s[mf][nf][0] - mn0);
                s[mf][nf][1] = ex2f(s[mf][nf][1] - mn0);
                s[mf][nf][2] = ex2f(s[mf][nf][2] - mn1);
                s[mf][nf][3] = ex2f(s[mf][nf][3] - mn1);
                rs0 += s[mf][nf][0] + s[mf][nf][1];
                rs1 += s[mf][nf][2] + s[mf][nf][3];
            }
            rs0 += __shfl_xor_sync(0xffffffffu, rs0, 1);
            rs0 += __shfl_xor_sync(0xffffffffu, rs0, 2);
            rs1 += __shfl_xor_sync(0xffffffffu, rs1, 1);
            rs1 += __shfl_xor_sync(0xffffffffu, rs1, 2);
            lrow[mf][0] = lrow[mf][0] * sc0 + rs0;
            lrow[mf][1] = lrow[mf][1] * sc1 + rs1;

#pragma unroll
            for (int nf = 0; nf < 8; nf++) {
                o[mf][nf][0] *= sc0; o[mf][nf][1] *= sc0;
                o[mf][nf][2] *= sc1; o[mf][nf][3] *= sc1;
            }

#pragma unroll
            for (int kf = 0; kf < 4; kf++) {
                const int n0 = 2 * kf, n1 = 2 * kf + 1;
                ph[mf][kf][0] = pack_h2(s[mf][n0][0], s[mf][n0][1]);
                ph[mf][kf][1] = pack_h2(s[mf][n0][2], s[mf][n0][3]);
                ph[mf][kf][2] = pack_h2(s[mf][n1][0], s[mf][n1][1]);
                ph[mf][kf][3] = pack_h2(s[mf][n1][2], s[mf][n1][3]);
            }
        }

        // ---- O += Ph Vh ----
#pragma unroll
        for (int kf = 0; kf < 4; kf++) {
            unsigned vh[4][4];
#pragma unroll
            for (int g4 = 0; g4 < 4; g4++) {
                const unsigned bo = (unsigned)(((g4 * 16 + lrB) * 72 + kf * 16 + lcB) * 2);
                ldm4(vh[g4], uVh + bo);
            }
#pragma unroll
            for (int nf = 0; nf < 8; nf++) {
                const unsigned* bf = &vh[nf >> 1][(nf & 1) * 2];
#pragma unroll
                for (int mf = 0; mf < 2; mf++)
                    MMA_F16(o[mf][nf], ph[mf][kf], bf);
            }
        }
    }

    // ---- epilogue: out[l][b][h*64 + d] ----
#pragma unroll
    for (int mf = 0; mf < 2; mf++) {
        const float inv0 = 1.0f / lrow[mf][0];
        const float inv1 = 1.0f / lrow[mf][1];
        const int r0 = q0 + rb0 + mf * 16 + g;
#pragma unroll
        for (int nf = 0; nf < 8; nf++) {
            const int col = h * 64 + nf * 8 + tg * 2;
            *reinterpret_cast<float2*>(out + (size_t)(r0 * 2 + b) * DMODEL + col) =
                make_float2(o[mf][nf][0] * inv0, o[mf][nf][1] * inv0);
            *reinterpret_cast<float2*>(out + (size_t)((r0 + 8) * 2 + b) * DMODEL + col) =
                make_float2(o[mf][nf][2] * inv1, o[mf][nf][3] * inv1);
        }
    }
}

// ---------------------------------------------------------------------------
extern "C" void kernel_launch(void* const* d_in, const int* in_sizes, int n_in,
                              void* d_out, int out_size) {
    const float* x = (const float*)d_in[0];
    const float* w = (const float*)d_in[1];
    if (n_in >= 2 && in_sizes[0] == E3 * DMODEL && in_sizes[1] == NROWS * DMODEL) {
        const float* t = x; x = w; w = t;
    }
    float* out = (float*)d_out;

    static bool attr_set = false;
    if (!attr_set) {
        cudaFuncSetAttribute(attn_tc, cudaFuncAttributeMaxDynamicSharedMemorySize,
                             ATTN_SMEM_BYTES);
        cudaFuncSetAttribute(qkv_gemm_tc, cudaFuncAttributeMaxDynamicSharedMemorySize,
                             QKV_SMEM);
        attr_set = true;
    }

    convert_xw<<<(NX4 + NW4) / 256, 256>>>(x, w);
    qkv_gemm_tc<<<dim3(E3 / 128, NROWS / 128), 256, QKV_SMEM>>>();
    prep_qkv<<<QK_BLOCKS + 1024, 256>>>();
    attn_tc<<<dim3(L_SEQ / 128, NHEADS, BATCH), 128, ATTN_SMEM_BYTES>>>(out);
}